// round 8
// baseline (speedup 1.0000x reference)
#include <cuda_runtime.h>

#define NL 50
#define THREADS 1024
#define ROWS_PER_CTA 2

// Edge integers: E_i = i for i<=25, else 25 + 7*(i-25); E_50 = 200.
// Edge floats computed exactly as numpy: (double)n / 200.0 * 0.6, cast to f32.
constexpr int   edge_int(int i) { return i <= 25 ? i : 25 + 7 * (i - 25); }
constexpr float edge_f(int i)   { return (float)((double)edge_int(i) / 200.0 * 0.6); }

#define E1(a)  edge_f(a)
#define E4(a)  E1(a), E1(a+1), E1(a+2), E1(a+3)
#define E16(a) E4(a), E4(a+4), E4(a+8), E4(a+12)
__constant__ float c_edges[51] = { E16(0), E16(16), E16(32), E1(48), E1(49), E1(50) };

// tbl[c] = {lo=E_c, hi=E_{c+1}, w=w_c, 0}. Fast path: one LDS.128.
// wext[j+1]: zero-padded weights for the ulp-rare off-by-one fallback.
__device__ __forceinline__ float bin_weight(float z,
                                            const float4* __restrict__ tbl,
                                            const float*  __restrict__ wext)
{
    if (z >= 0.6f || z <= 0.0f) return 0.0f;       // outside all bins, no LDS
    float t = z * (200.0f / 0.6f);
    int c = (t < 25.0f) ? (int)t : 25 + (int)((t - 25.0f) * (1.0f / 7.0f));
    c = min(c, NL - 1);
    float4 q = tbl[c];
    float w = q.z;
    if (!(z > q.x && z < q.y)) {                   // candidate off by one (rare)
        int j = (z >= q.y) ? c + 1 : c - 1;        // j in [-1, 50]
        w = wext[j + 1];
    }
    return w;
}

__global__ __launch_bounds__(THREADS) void zws_kernel(
    const float4* __restrict__ x,      // (B, V/2) float4 = 2 (z,val) pairs
    const float*  __restrict__ weight, // (NL,)
    const float*  __restrict__ bias,   // (NL,)
    float*        __restrict__ out,    // (B,)
    int nf4_per_row,                   // V/2 (= 2048)
    int B)
{
    __shared__ float4 tbl[NL];
    __shared__ float  wext[NL + 2];
    __shared__ float  red0[THREADS / 32];
    __shared__ float  red1[THREADS / 32];

    const int tid = threadIdx.x;
    const int r0  = blockIdx.x * ROWS_PER_CTA;
    const int r1  = r0 + 1;
    const bool has_r1 = (r1 < B);

    const float4* row0 = x + (size_t)r0 * nf4_per_row;
    const float4* row1 = x + (size_t)(has_r1 ? r1 : r0) * nf4_per_row;

    // ---- Front-batch all 4 independent loads (2 per row) before any table work ----
    const int i0 = tid;
    const int i1 = tid + THREADS;
    float4 a0 = make_float4(0.f, 0.f, 0.f, 0.f);
    float4 a1 = make_float4(0.f, 0.f, 0.f, 0.f);
    float4 b0 = make_float4(0.f, 0.f, 0.f, 0.f);
    float4 b1 = make_float4(0.f, 0.f, 0.f, 0.f);
    if (i0 < nf4_per_row) a0 = __ldg(&row0[i0]);
    if (i1 < nf4_per_row) a1 = __ldg(&row0[i1]);
    if (has_r1) {
        if (i0 < nf4_per_row) b0 = __ldg(&row1[i0]);
        if (i1 < nf4_per_row) b1 = __ldg(&row1[i1]);
    }

    // ---- Table setup overlaps the DRAM latency of the bulk loads ----
    float acc0 = 0.0f, acc1 = 0.0f;
    if (tid < NL) {
        float w = weight[tid];
        tbl[tid]      = make_float4(c_edges[tid], c_edges[tid + 1], w, 0.0f);
        wext[tid + 1] = w;
        float d = bias[tid] * w;                   // fold dot(bias, weight)
        acc0 = d;
        acc1 = d;
    }
    if (tid == 0) { wext[0] = 0.0f; wext[NL + 1] = 0.0f; }
    __syncthreads();

    acc0 = fmaf(a0.y, bin_weight(a0.x, tbl, wext), acc0);
    acc0 = fmaf(a0.w, bin_weight(a0.z, tbl, wext), acc0);
    acc0 = fmaf(a1.y, bin_weight(a1.x, tbl, wext), acc0);
    acc0 = fmaf(a1.w, bin_weight(a1.z, tbl, wext), acc0);

    acc1 = fmaf(b0.y, bin_weight(b0.x, tbl, wext), acc1);
    acc1 = fmaf(b0.w, bin_weight(b0.z, tbl, wext), acc1);
    acc1 = fmaf(b1.y, bin_weight(b1.x, tbl, wext), acc1);
    acc1 = fmaf(b1.w, bin_weight(b1.z, tbl, wext), acc1);

    // Tail for nonstandard shapes (not executed for V=4096).
    for (int i = tid + 2 * THREADS; i < nf4_per_row; i += THREADS) {
        float4 p = __ldg(&row0[i]);
        acc0 = fmaf(p.y, bin_weight(p.x, tbl, wext), acc0);
        acc0 = fmaf(p.w, bin_weight(p.z, tbl, wext), acc0);
        if (has_r1) {
            float4 q = __ldg(&row1[i]);
            acc1 = fmaf(q.y, bin_weight(q.x, tbl, wext), acc1);
            acc1 = fmaf(q.w, bin_weight(q.z, tbl, wext), acc1);
        }
    }

    // ---- Dual block reduction (32 warps) ----
    #pragma unroll
    for (int o = 16; o; o >>= 1) {
        acc0 += __shfl_down_sync(0xFFFFFFFFu, acc0, o);
        acc1 += __shfl_down_sync(0xFFFFFFFFu, acc1, o);
    }
    if ((tid & 31) == 0) { red0[tid >> 5] = acc0; red1[tid >> 5] = acc1; }
    __syncthreads();

    if (tid < 32) {                                // warp 0 -> row 0
        float v = red0[tid];
        #pragma unroll
        for (int o = 16; o; o >>= 1)
            v += __shfl_down_sync(0xFFFFFFFFu, v, o);
        if (tid == 0) out[r0] = v;
    } else if (tid < 64 && has_r1) {               // warp 1 -> row 1
        float v = red1[tid - 32];
        #pragma unroll
        for (int o = 16; o; o >>= 1)
            v += __shfl_down_sync(0xFFFFFFFFu, v, o);
        if (tid == 32) out[r1] = v;
    }
}

extern "C" void kernel_launch(void* const* d_in, const int* in_sizes, int n_in,
                              void* d_out, int out_size)
{
    const float4* x      = (const float4*)d_in[0];  // (B, V, 2) float32
    const float*  weight = (const float*)d_in[1];   // (NL, 1)
    const float*  bias   = (const float*)d_in[2];   // (NL,)
    float*        out    = (float*)d_out;           // (B,)

    const int B = out_size;                          // 256
    const int pairs_total = in_sizes[0] / 2;         // B * V
    const int nf4_per_row = pairs_total / B / 2;     // V / 2 = 2048

    const int grid = (B + ROWS_PER_CTA - 1) / ROWS_PER_CTA;   // 128
    zws_kernel<<<grid, THREADS>>>(x, weight, bias, out, nf4_per_row, B);
}